// round 1
// baseline (speedup 1.0000x reference)
#include <cuda_runtime.h>
#include <math.h>

#define FDIM 512
#define NADJ 512
#define MROWS 65536
#define SP 132   // smem pitch for K-major tiles (132*4B multiple of 16 -> LDS.128 ok)

// ---------------- scratch (device globals; no runtime allocation) ----------------
__device__ float g_h1[(size_t)MROWS * FDIM];     // 128 MiB: lrelu(bn1(d@W1^T))
__device__ float g_cpart[4][(size_t)MROWS * 2];  // partial Wc projections per column-block
__device__ float g_wnT[NADJ * NADJ];             // w_norm transposed: wnT[n][m] = w_norm[m][n]
__device__ float g_dinv[NADJ];
__device__ float g_sb[4 * FDIM];                 // s1, t1, s2, t2 (folded BN affine)

// ---------------- small prep kernels ----------------
__global__ void prep_scales_kernel(const float* b1, const float* g1, const float* be1,
                                   const float* m1, const float* v1,
                                   const float* b2, const float* g2, const float* be2,
                                   const float* m2, const float* v2) {
    int f = threadIdx.x;
    float s1 = g1[f] * rsqrtf(v1[f] + 1e-5f);
    g_sb[f]        = s1;
    g_sb[FDIM + f] = (b1[f] - m1[f]) * s1 + be1[f];
    float s2 = g2[f] * rsqrtf(v2[f] + 1e-5f);
    g_sb[2*FDIM + f] = s2;
    g_sb[3*FDIM + f] = (b2[f] - m2[f]) * s2 + be2[f];
}

__global__ void rowsum_kernel(const float* __restrict__ w) {
    __shared__ float red[128];
    int i = blockIdx.x;
    float s = 0.f;
    for (int j = threadIdx.x; j < NADJ; j += 128) s += w[i * NADJ + j];
    red[threadIdx.x] = s;
    __syncthreads();
    for (int o = 64; o > 0; o >>= 1) {
        if (threadIdx.x < o) red[threadIdx.x] += red[threadIdx.x + o];
        __syncthreads();
    }
    if (threadIdx.x == 0) {
        float tot = red[0] + 1.0f;                 // + identity diagonal
        float di = rsqrtf(tot);
        if (isinf(di)) di = 0.f;
        g_dinv[i] = di;
    }
}

__global__ void wnorm_kernel(const float* __restrict__ w) {
    int idx = blockIdx.x * blockDim.x + threadIdx.x;   // 0 .. 512*512-1
    int n = idx >> 9, m = idx & 511;
    float a = w[n * NADJ + m] + (n == m ? 1.f : 0.f);  // adj[n][m]
    // w_norm[m][n] = adj[n][m] * dinv[m] * dinv[n]  -> wnT[n][m]
    g_wnT[idx] = a * g_dinv[n] * g_dinv[m];
}

// ---------------- GEMM1: g_h1 = lrelu((d @ W1^T) * s1 + t1) ----------------
// C-tile 128x128, K-tile 16, 256 threads, 8x8 per thread, register prefetch.
__global__ __launch_bounds__(256, 2) void gemm1_kernel(const float* __restrict__ A,
                                                       const float* __restrict__ W) {
    __shared__ float As[16 * SP];
    __shared__ float Bs[16 * SP];
    const int bm = blockIdx.y << 7;
    const int bn = blockIdx.x << 7;
    const int tid = threadIdx.x;
    const int tx = tid & 15, ty = tid >> 4;
    const int lr = tid >> 2;          // 0..63
    const int lk = (tid & 3) << 2;    // 0,4,8,12
    const float* Ab = A + (size_t)(bm) * FDIM + lk;
    const float* Wb = W + (size_t)(bn) * FDIM + lk;

    float4 pa0 = *(const float4*)(Ab + (size_t)lr * FDIM);
    float4 pa1 = *(const float4*)(Ab + (size_t)(lr + 64) * FDIM);
    float4 pb0 = *(const float4*)(Wb + (size_t)lr * FDIM);
    float4 pb1 = *(const float4*)(Wb + (size_t)(lr + 64) * FDIM);

    float acc[8][8];
#pragma unroll
    for (int i = 0; i < 8; i++)
#pragma unroll
        for (int j = 0; j < 8; j++) acc[i][j] = 0.f;

#pragma unroll 1
    for (int kt = 0; kt < 32; kt++) {
        As[(lk+0)*SP + lr] = pa0.x; As[(lk+1)*SP + lr] = pa0.y;
        As[(lk+2)*SP + lr] = pa0.z; As[(lk+3)*SP + lr] = pa0.w;
        As[(lk+0)*SP + lr+64] = pa1.x; As[(lk+1)*SP + lr+64] = pa1.y;
        As[(lk+2)*SP + lr+64] = pa1.z; As[(lk+3)*SP + lr+64] = pa1.w;
        Bs[(lk+0)*SP + lr] = pb0.x; Bs[(lk+1)*SP + lr] = pb0.y;
        Bs[(lk+2)*SP + lr] = pb0.z; Bs[(lk+3)*SP + lr] = pb0.w;
        Bs[(lk+0)*SP + lr+64] = pb1.x; Bs[(lk+1)*SP + lr+64] = pb1.y;
        Bs[(lk+2)*SP + lr+64] = pb1.z; Bs[(lk+3)*SP + lr+64] = pb1.w;
        __syncthreads();

        if (kt < 31) {
            int ko = (kt + 1) << 4;
            pa0 = *(const float4*)(Ab + (size_t)lr * FDIM + ko);
            pa1 = *(const float4*)(Ab + (size_t)(lr + 64) * FDIM + ko);
            pb0 = *(const float4*)(Wb + (size_t)lr * FDIM + ko);
            pb1 = *(const float4*)(Wb + (size_t)(lr + 64) * FDIM + ko);
        }
#pragma unroll
        for (int kk = 0; kk < 16; kk++) {
            float a[8], b[8];
            *(float4*)&a[0] = *(const float4*)&As[kk*SP + (ty<<3)];
            *(float4*)&a[4] = *(const float4*)&As[kk*SP + (ty<<3) + 4];
            *(float4*)&b[0] = *(const float4*)&Bs[kk*SP + (tx<<3)];
            *(float4*)&b[4] = *(const float4*)&Bs[kk*SP + (tx<<3) + 4];
#pragma unroll
            for (int i = 0; i < 8; i++)
#pragma unroll
                for (int j = 0; j < 8; j++) acc[i][j] = fmaf(a[i], b[j], acc[i][j]);
        }
        __syncthreads();
    }

    // epilogue: BN affine + LeakyReLU, coalesced float4 stores
    const int rbase = bm + (ty << 3);
    const int cbase = bn + (tx << 3);
    float s[8], t[8];
#pragma unroll
    for (int j = 0; j < 8; j++) { s[j] = g_sb[cbase + j]; t[j] = g_sb[FDIM + cbase + j]; }
#pragma unroll
    for (int i = 0; i < 8; i++) {
        float o[8];
#pragma unroll
        for (int j = 0; j < 8; j++) {
            float v = fmaf(acc[i][j], s[j], t[j]);
            o[j] = v > 0.f ? v : 0.1f * v;
        }
        float* dst = &g_h1[(size_t)(rbase + i) * FDIM + cbase];
        *(float4*)dst       = make_float4(o[0], o[1], o[2], o[3]);
        *(float4*)(dst + 4) = make_float4(o[4], o[5], o[6], o[7]);
    }
}

// ---------------- GEMM2: h2 = lrelu((h1 @ W2^T)*s2 + t2) fused with Wc projection ----------------
// Writes partial c[row][k] (k in {0,1}) per column-block into g_cpart — h2 never hits HBM.
__global__ __launch_bounds__(256, 2) void gemm2_kernel(const float* __restrict__ W,
                                                       const float* __restrict__ Wc) {
    __shared__ float As[16 * SP];
    __shared__ float Bs[16 * SP];
    __shared__ float red[128 * 33];
    const int bm = blockIdx.y << 7;
    const int bn = blockIdx.x << 7;
    const int tid = threadIdx.x;
    const int tx = tid & 15, ty = tid >> 4;
    const int lr = tid >> 2;
    const int lk = (tid & 3) << 2;
    const float* Ab = g_h1 + (size_t)(bm) * FDIM + lk;
    const float* Wb = W + (size_t)(bn) * FDIM + lk;

    float4 pa0 = *(const float4*)(Ab + (size_t)lr * FDIM);
    float4 pa1 = *(const float4*)(Ab + (size_t)(lr + 64) * FDIM);
    float4 pb0 = *(const float4*)(Wb + (size_t)lr * FDIM);
    float4 pb1 = *(const float4*)(Wb + (size_t)(lr + 64) * FDIM);

    float acc[8][8];
#pragma unroll
    for (int i = 0; i < 8; i++)
#pragma unroll
        for (int j = 0; j < 8; j++) acc[i][j] = 0.f;

#pragma unroll 1
    for (int kt = 0; kt < 32; kt++) {
        As[(lk+0)*SP + lr] = pa0.x; As[(lk+1)*SP + lr] = pa0.y;
        As[(lk+2)*SP + lr] = pa0.z; As[(lk+3)*SP + lr] = pa0.w;
        As[(lk+0)*SP + lr+64] = pa1.x; As[(lk+1)*SP + lr+64] = pa1.y;
        As[(lk+2)*SP + lr+64] = pa1.z; As[(lk+3)*SP + lr+64] = pa1.w;
        Bs[(lk+0)*SP + lr] = pb0.x; Bs[(lk+1)*SP + lr] = pb0.y;
        Bs[(lk+2)*SP + lr] = pb0.z; Bs[(lk+3)*SP + lr] = pb0.w;
        Bs[(lk+0)*SP + lr+64] = pb1.x; Bs[(lk+1)*SP + lr+64] = pb1.y;
        Bs[(lk+2)*SP + lr+64] = pb1.z; Bs[(lk+3)*SP + lr+64] = pb1.w;
        __syncthreads();

        if (kt < 31) {
            int ko = (kt + 1) << 4;
            pa0 = *(const float4*)(Ab + (size_t)lr * FDIM + ko);
            pa1 = *(const float4*)(Ab + (size_t)(lr + 64) * FDIM + ko);
            pb0 = *(const float4*)(Wb + (size_t)lr * FDIM + ko);
            pb1 = *(const float4*)(Wb + (size_t)(lr + 64) * FDIM + ko);
        }
#pragma unroll
        for (int kk = 0; kk < 16; kk++) {
            float a[8], b[8];
            *(float4*)&a[0] = *(const float4*)&As[kk*SP + (ty<<3)];
            *(float4*)&a[4] = *(const float4*)&As[kk*SP + (ty<<3) + 4];
            *(float4*)&b[0] = *(const float4*)&Bs[kk*SP + (tx<<3)];
            *(float4*)&b[4] = *(const float4*)&Bs[kk*SP + (tx<<3) + 4];
#pragma unroll
            for (int i = 0; i < 8; i++)
#pragma unroll
                for (int j = 0; j < 8; j++) acc[i][j] = fmaf(a[i], b[j], acc[i][j]);
        }
        __syncthreads();
    }

    // epilogue: BN affine + LeakyReLU + dot with Wc rows -> per-thread partials
    const int cbase = bn + (tx << 3);
    float pr0[8], pr1[8];
#pragma unroll
    for (int i = 0; i < 8; i++) { pr0[i] = 0.f; pr1[i] = 0.f; }
#pragma unroll
    for (int j = 0; j < 8; j++) {
        int col = cbase + j;
        float s  = g_sb[2*FDIM + col];
        float t  = g_sb[3*FDIM + col];
        float w0 = Wc[col];
        float w1 = Wc[FDIM + col];
#pragma unroll
        for (int i = 0; i < 8; i++) {
            float v = fmaf(acc[i][j], s, t);
            v = v > 0.f ? v : 0.1f * v;
            pr0[i] = fmaf(v, w0, pr0[i]);
            pr1[i] = fmaf(v, w1, pr1[i]);
        }
    }
    // block-wide reduction across the 16 tx columns
#pragma unroll
    for (int i = 0; i < 8; i++) {
        int r = (ty << 3) + i;
        red[r * 33 + tx * 2]     = pr0[i];
        red[r * 33 + tx * 2 + 1] = pr1[i];
    }
    __syncthreads();
    int row = tid >> 1, k = tid & 1;
    float sum = 0.f;
#pragma unroll
    for (int q = 0; q < 16; q++) sum += red[row * 33 + q * 2 + k];
    g_cpart[blockIdx.x][(size_t)(bm + row) * 2 + k] = sum;
}

// ---------------- GCN propagation on the 2-column projection + bias ----------------
// out[(b*512+n)*2+k] = bc[k] + sum_m wnT[n][m] * c[b][m][k]
__global__ __launch_bounds__(512) void gcn_kernel(const float* __restrict__ bc,
                                                  float* __restrict__ out) {
    __shared__ float2 cs[NADJ];
    int b = blockIdx.x;
    int t = threadIdx.x;
    {
        float2 v = make_float2(0.f, 0.f);
        size_t base = (size_t)b * (NADJ * 2) + t * 2;
#pragma unroll
        for (int nb = 0; nb < 4; nb++) {
            v.x += g_cpart[nb][base];
            v.y += g_cpart[nb][base + 1];
        }
        cs[t] = v;
    }
    __syncthreads();
    float a0 = bc[0], a1 = bc[1];
    const float4* wr4 = (const float4*)(g_wnT + (size_t)t * NADJ);
#pragma unroll 4
    for (int m4 = 0; m4 < NADJ / 4; m4++) {
        float4 wv = wr4[m4];
        float2 c0 = cs[m4*4+0], c1 = cs[m4*4+1], c2 = cs[m4*4+2], c3 = cs[m4*4+3];
        a0 = fmaf(wv.x, c0.x, a0); a1 = fmaf(wv.x, c0.y, a1);
        a0 = fmaf(wv.y, c1.x, a0); a1 = fmaf(wv.y, c1.y, a1);
        a0 = fmaf(wv.z, c2.x, a0); a1 = fmaf(wv.z, c2.y, a1);
        a0 = fmaf(wv.w, c3.x, a0); a1 = fmaf(wv.w, c3.y, a1);
    }
    size_t o = ((size_t)b * NADJ + t) * 2;
    out[o]     = a0;
    out[o + 1] = a1;
}

// ---------------- launch ----------------
extern "C" void kernel_launch(void* const* d_in, const int* in_sizes, int n_in,
                              void* d_out, int out_size) {
    const float* d   = (const float*)d_in[0];
    const float* w   = (const float*)d_in[1];
    const float* W1  = (const float*)d_in[2];
    const float* b1  = (const float*)d_in[3];
    const float* g1  = (const float*)d_in[4];
    const float* be1 = (const float*)d_in[5];
    const float* m1  = (const float*)d_in[6];
    const float* v1  = (const float*)d_in[7];
    const float* W2  = (const float*)d_in[8];
    const float* b2  = (const float*)d_in[9];
    const float* g2  = (const float*)d_in[10];
    const float* be2 = (const float*)d_in[11];
    const float* m2  = (const float*)d_in[12];
    const float* v2  = (const float*)d_in[13];
    const float* Wc  = (const float*)d_in[14];
    const float* bc  = (const float*)d_in[15];
    float* out = (float*)d_out;

    prep_scales_kernel<<<1, FDIM>>>(b1, g1, be1, m1, v1, b2, g2, be2, m2, v2);
    rowsum_kernel<<<NADJ, 128>>>(w);
    wnorm_kernel<<<(NADJ * NADJ) / 256, 256>>>(w);
    gemm1_kernel<<<dim3(4, MROWS / 128), 256>>>(d, W1);
    gemm2_kernel<<<dim3(4, MROWS / 128), 256>>>(W2, Wc);
    gcn_kernel<<<128, 512>>>(bc, out);
}

// round 3
// speedup vs baseline: 2.0136x; 2.0136x over previous
#include <cuda_runtime.h>
#include <cuda_bf16.h>
#include <stdint.h>
#include <math.h>

#define FDIM 512
#define NADJ 512
#define MROWS 65536

// ======================= helpers =======================
__device__ __forceinline__ uint32_t smem_u32(const void* p) {
    uint32_t a;
    asm("{ .reg .u64 t; cvta.to.shared.u64 t, %1; cvt.u32.u64 %0, t; }" : "=r"(a) : "l"(p));
    return a;
}
#define CP_ASYNC16(sa, ga) asm volatile("cp.async.cg.shared.global [%0], [%1], 16;" :: "r"(sa), "l"(ga) : "memory")
#define CP_COMMIT()        asm volatile("cp.async.commit_group;" ::: "memory")
#define CP_WAIT(n)         asm volatile("cp.async.wait_group %0;" :: "n"(n) : "memory")

#define LDSM4(r0, r1, r2, r3, addr) \
    asm volatile("ldmatrix.sync.aligned.m8n8.x4.shared.b16 {%0,%1,%2,%3}, [%4];" \
        : "=r"(r0), "=r"(r1), "=r"(r2), "=r"(r3) : "r"(addr))

#define MMA16816(d, a, b0, b1) \
    asm volatile("mma.sync.aligned.m16n8k16.row.col.f32.bf16.bf16.f32 " \
        "{%0,%1,%2,%3}, {%4,%5,%6,%7}, {%8,%9}, {%0,%1,%2,%3};" \
        : "+f"((d)[0]), "+f"((d)[1]), "+f"((d)[2]), "+f"((d)[3]) \
        : "r"((a)[0]), "r"((a)[1]), "r"((a)[2]), "r"((a)[3]), "r"(b0), "r"(b1))

__device__ __forceinline__ uint32_t pack2(float a, float b) {
    __nv_bfloat162 t = __floats2bfloat162_rn(a, b);
    return *reinterpret_cast<uint32_t*>(&t);
}

// ======================= device scratch =======================
__device__ __nv_bfloat16 g_a2[(size_t)MROWS * 1024];   // d split: [r][0:512)=hi, [512:1024)=lo
__device__ __nv_bfloat16 g_h1s[(size_t)MROWS * 1024];  // h1 split, same layout
__device__ __nv_bfloat16 g_b1s[NADJ * 1536];           // W1: [n][hi|lo|hi]
__device__ __nv_bfloat16 g_b2s[NADJ * 1536];           // W2: [n][hi|lo|hi]
__device__ float g_cpart[4][(size_t)MROWS * 2];
__device__ float g_wnT[NADJ * NADJ];
__device__ float g_dinv[NADJ];
__device__ float g_sb[4 * FDIM];   // s1, t1, s2, t2

// ======================= small prep kernels =======================
__global__ void prep_scales_kernel(const float* b1, const float* g1, const float* be1,
                                   const float* m1, const float* v1,
                                   const float* b2, const float* g2, const float* be2,
                                   const float* m2, const float* v2) {
    int f = threadIdx.x;
    float s1 = g1[f] * rsqrtf(v1[f] + 1e-5f);
    g_sb[f]        = s1;
    g_sb[FDIM + f] = (b1[f] - m1[f]) * s1 + be1[f];
    float s2 = g2[f] * rsqrtf(v2[f] + 1e-5f);
    g_sb[2*FDIM + f] = s2;
    g_sb[3*FDIM + f] = (b2[f] - m2[f]) * s2 + be2[f];
}

__global__ void rowsum_kernel(const float* __restrict__ w) {
    __shared__ float red[128];
    int i = blockIdx.x;
    float s = 0.f;
    for (int j = threadIdx.x; j < NADJ; j += 128) s += w[i * NADJ + j];
    red[threadIdx.x] = s;
    __syncthreads();
    for (int o = 64; o > 0; o >>= 1) {
        if (threadIdx.x < o) red[threadIdx.x] += red[threadIdx.x + o];
        __syncthreads();
    }
    if (threadIdx.x == 0) {
        float di = rsqrtf(red[0] + 1.0f);
        if (isinf(di)) di = 0.f;
        g_dinv[i] = di;
    }
}

__global__ void wnorm_kernel(const float* __restrict__ w) {
    int idx = blockIdx.x * blockDim.x + threadIdx.x;
    int n = idx >> 9, m = idx & 511;
    float a = w[n * NADJ + m] + (n == m ? 1.f : 0.f);
    g_wnT[idx] = a * g_dinv[n] * g_dinv[m];   // wnT[n][m] = w_norm[m][n]
}

// split d (fp32) -> g_a2 (bf16 hi|lo)
__global__ void split_d_kernel(const float4* __restrict__ d) {
    size_t idx = (size_t)blockIdx.x * blockDim.x + threadIdx.x;  // 8388608 float4s
    float4 v = d[idx];
    size_t r = idx >> 7;
    int kq = (int)(idx & 127);
    float hx = __bfloat162float(__float2bfloat16(v.x));
    float hy = __bfloat162float(__float2bfloat16(v.y));
    float hz = __bfloat162float(__float2bfloat16(v.z));
    float hw = __bfloat162float(__float2bfloat16(v.w));
    uint2 hp = make_uint2(pack2(hx, hy), pack2(hz, hw));
    uint2 lp = make_uint2(pack2(v.x - hx, v.y - hy), pack2(v.z - hz, v.w - hw));
    uint2* base = (uint2*)g_a2;
    base[r * 256 + kq]       = hp;
    base[r * 256 + 128 + kq] = lp;
}

// split W -> [n][hi(512) | lo(512) | hi(512)]
__global__ void split_w_kernel(const float* __restrict__ W, int which) {
    int idx = blockIdx.x * blockDim.x + threadIdx.x;  // 262144
    int n = idx >> 9, k = idx & 511;
    float x = W[idx];
    float hf = __bfloat162float(__float2bfloat16(x));
    __nv_bfloat16 h = __float2bfloat16(hf);
    __nv_bfloat16 l = __float2bfloat16(x - hf);
    __nv_bfloat16* out = which ? g_b2s : g_b1s;
    size_t base = (size_t)n * 1536;
    out[base + k] = h;
    out[base + 512 + k] = l;
    out[base + 1024 + k] = h;
}

// ======================= HMMA GEMM =======================
// C[128 x 128] per block. K_eff = 1536 in 48 k-tiles of 32.
// 256 threads = 8 warps as 2(M) x 4(N); warp tile 64x32 via m16n8k16.
// 4-stage cp.async pipeline. smem pitch 80 B (conflict-free ldmatrix phases).
#define KTILES 48
#define PITCH  80
#define HALF_STAGE (128 * PITCH)          // 10240 B (A), same for B
#define STAGE_B (2 * HALF_STAGE)          // 20480 B
#define SMEM_B  (4 * STAGE_B)             // 81920 B

template <int MODE>
__global__ __launch_bounds__(256, 2) void gemm_hmma(const float* __restrict__ Wc) {
    extern __shared__ char dsmem[];
    __shared__ float red[128][2];
    const int tid = threadIdx.x;
    const int wid = tid >> 5;
    const int lane = tid & 31;
    const int bm = blockIdx.y << 7;
    const int bn = blockIdx.x << 7;
    const int moff = (wid & 1) << 6;      // 0 or 64
    const int noff = (wid >> 1) << 5;     // 0,32,64,96
    const uint32_t sbase = smem_u32(dsmem);

    const __nv_bfloat16* __restrict__ A = (MODE == 1) ? g_a2 : g_h1s;
    const __nv_bfloat16* __restrict__ B = (MODE == 1) ? g_b1s : g_b2s;

    // per-thread cp.async chunk coords (2 chunks of 16B each for A and B)
    const int c0row = tid >> 2, c0kc = tid & 3;
    const int c1row = (tid + 256) >> 2, c1kc = tid & 3;

    auto issue = [&](int t) {
        const int s = t & 3;
        const int koffA = (t < 32) ? ((t & 15) << 5) : (512 + ((t - 32) << 5));
        const int koffB = t << 5;
        const uint32_t stA = sbase + s * STAGE_B;
        const uint32_t stB = stA + HALF_STAGE;
        CP_ASYNC16(stA + c0row * PITCH + c0kc * 16, A + (size_t)(bm + c0row) * 1024 + koffA + c0kc * 8);
        CP_ASYNC16(stB + c0row * PITCH + c0kc * 16, B + (size_t)(bn + c0row) * 1536 + koffB + c0kc * 8);
        CP_ASYNC16(stA + c1row * PITCH + c1kc * 16, A + (size_t)(bm + c1row) * 1024 + koffA + c1kc * 8);
        CP_ASYNC16(stB + c1row * PITCH + c1kc * 16, B + (size_t)(bn + c1row) * 1536 + koffB + c1kc * 8);
        CP_COMMIT();
    };

    float acc[4][4][4];
#pragma unroll
    for (int i = 0; i < 4; i++)
#pragma unroll
        for (int j = 0; j < 4; j++)
#pragma unroll
            for (int r = 0; r < 4; r++) acc[i][j][r] = 0.f;

    issue(0); issue(1); issue(2);

    // precomputed ldmatrix lane addressing
    const int a_row = lane & 15;                 // A: rows m..m+15
    const int a_kb  = ((lane >> 4) & 1) << 4;    // 0 or 16 bytes (k half)
    const int q     = lane >> 3;                 // B quad: 0..3
    const int b_row = ((q >> 1) << 3) + (lane & 7);
    const int b_kb  = (q & 1) << 4;

#pragma unroll 1
    for (int t = 0; t < KTILES; t++) {
        if (t < KTILES - 2)      CP_WAIT(2);
        else if (t == KTILES-2)  CP_WAIT(1);
        else                     CP_WAIT(0);
        __syncthreads();
        if (t + 3 < KTILES) issue(t + 3);

        const uint32_t sA = sbase + (t & 3) * STAGE_B;
        const uint32_t sB = sA + HALF_STAGE;
#pragma unroll
        for (int ks = 0; ks < 2; ks++) {
            uint32_t a[4][4];
            uint32_t b[2][4];
#pragma unroll
            for (int mi = 0; mi < 4; mi++) {
                uint32_t addr = sA + (uint32_t)(moff + mi * 16 + a_row) * PITCH + ks * 32 + a_kb;
                LDSM4(a[mi][0], a[mi][1], a[mi][2], a[mi][3], addr);
            }
#pragma unroll
            for (int p = 0; p < 2; p++) {
                uint32_t addr = sB + (uint32_t)(noff + p * 16 + b_row) * PITCH + ks * 32 + b_kb;
                LDSM4(b[p][0], b[p][1], b[p][2], b[p][3], addr);
            }
#pragma unroll
            for (int mi = 0; mi < 4; mi++) {
#pragma unroll
                for (int ni = 0; ni < 4; ni++) {
                    MMA16816(acc[mi][ni], a[mi], b[ni >> 1][(ni & 1) * 2], b[ni >> 1][(ni & 1) * 2 + 1]);
                }
            }
        }
    }

    // ---------------- epilogue ----------------
    const int row0 = moff + ((lane >> 2));       // local row base
    const int col0 = noff + ((lane & 3) << 1);   // local col base (even)

    if (MODE == 1) {
#pragma unroll
        for (int mi = 0; mi < 4; mi++) {
#pragma unroll
            for (int h = 0; h < 2; h++) {
                const size_t r = (size_t)bm + row0 + mi * 16 + h * 8;
#pragma unroll
                for (int ni = 0; ni < 4; ni++) {
                    const int col = bn + col0 + ni * 8;
                    float v0 = fmaf(acc[mi][ni][h * 2],     g_sb[col],     g_sb[FDIM + col]);
                    float v1 = fmaf(acc[mi][ni][h * 2 + 1], g_sb[col + 1], g_sb[FDIM + col + 1]);
                    v0 = v0 > 0.f ? v0 : 0.1f * v0;
                    v1 = v1 > 0.f ? v1 : 0.1f * v1;
                    float h0 = __bfloat162float(__float2bfloat16(v0));
                    float h1 = __bfloat162float(__float2bfloat16(v1));
                    *(uint32_t*)&g_h1s[r * 1024 + col]       = pack2(h0, h1);
                    *(uint32_t*)&g_h1s[r * 1024 + 512 + col] = pack2(v0 - h0, v1 - h1);
                }
            }
        }
    } else {
        __syncthreads();
        if (tid < 256) { red[tid >> 1][tid & 1] = 0.f; }
        __syncthreads();
#pragma unroll
        for (int mi = 0; mi < 4; mi++) {
#pragma unroll
            for (int h = 0; h < 2; h++) {
                float p0 = 0.f, p1 = 0.f;
#pragma unroll
                for (int ni = 0; ni < 4; ni++) {
                    const int col = bn + col0 + ni * 8;
                    float v0 = fmaf(acc[mi][ni][h * 2],     g_sb[2*FDIM + col],     g_sb[3*FDIM + col]);
                    float v1 = fmaf(acc[mi][ni][h * 2 + 1], g_sb[2*FDIM + col + 1], g_sb[3*FDIM + col + 1]);
                    v0 = v0 > 0.f ? v0 : 0.1f * v0;
                    v1 = v1 > 0.f ? v1 : 0.1f * v1;
                    p0 = fmaf(v0, Wc[col], p0);        p0 = fmaf(v1, Wc[col + 1], p0);
                    p1 = fmaf(v0, Wc[FDIM + col], p1); p1 = fmaf(v1, Wc[FDIM + col + 1], p1);
                }
                // reduce across the 4 lanes sharing this row (lane&3 varies)
                p0 += __shfl_xor_sync(0xFFFFFFFF, p0, 1); p0 += __shfl_xor_sync(0xFFFFFFFF, p0, 2);
                p1 += __shfl_xor_sync(0xFFFFFFFF, p1, 1); p1 += __shfl_xor_sync(0xFFFFFFFF, p1, 2);
                if ((lane & 3) == 0) {
                    const int rl = row0 + mi * 16 + h * 8;
                    atomicAdd(&red[rl][0], p0);
                    atomicAdd(&red[rl][1], p1);
                }
            }
        }
        __syncthreads();
        if (tid < 256) {
            const int rl = tid >> 1, k = tid & 1;
            g_cpart[blockIdx.x][((size_t)bm + rl) * 2 + k] = red[rl][k];
        }
    }
}

// ======================= GCN propagation + bias =======================
__global__ __launch_bounds__(512) void gcn_kernel(const float* __restrict__ bc,
                                                  float* __restrict__ out) {
    __shared__ float2 cs[NADJ];
    int b = blockIdx.x;
    int t = threadIdx.x;
    {
        float2 v = make_float2(0.f, 0.f);
        size_t base = (size_t)b * (NADJ * 2) + t * 2;
#pragma unroll
        for (int nb = 0; nb < 4; nb++) {
            v.x += g_cpart[nb][base];
            v.y += g_cpart[nb][base + 1];
        }
        cs[t] = v;
    }
    __syncthreads();
    float a0 = bc[0], a1 = bc[1];
    const float4* wr4 = (const float4*)(g_wnT + (size_t)t * NADJ);
#pragma unroll 4
    for (int m4 = 0; m4 < NADJ / 4; m4++) {
        float4 wv = wr4[m4];
        float2 c0 = cs[m4*4+0], c1 = cs[m4*4+1], c2 = cs[m4*4+2], c3 = cs[m4*4+3];
        a0 = fmaf(wv.x, c0.x, a0); a1 = fmaf(wv.x, c0.y, a1);
        a0 = fmaf(wv.y, c1.x, a0); a1 = fmaf(wv.y, c1.y, a1);
        a0 = fmaf(wv.z, c2.x, a0); a1 = fmaf(wv.z, c2.y, a1);
        a0 = fmaf(wv.w, c3.x, a0); a1 = fmaf(wv.w, c3.y, a1);
    }
    size_t o = ((size_t)b * NADJ + t) * 2;
    out[o]     = a0;
    out[o + 1] = a1;
}

// ======================= launch =======================
extern "C" void kernel_launch(void* const* d_in, const int* in_sizes, int n_in,
                              void* d_out, int out_size) {
    const float* d   = (const float*)d_in[0];
    const float* w   = (const float*)d_in[1];
    const float* W1  = (const float*)d_in[2];
    const float* b1  = (const float*)d_in[3];
    const float* g1  = (const float*)d_in[4];
    const float* be1 = (const float*)d_in[5];
    const float* m1  = (const float*)d_in[6];
    const float* v1  = (const float*)d_in[7];
    const float* W2  = (const float*)d_in[8];
    const float* b2  = (const float*)d_in[9];
    const float* g2  = (const float*)d_in[10];
    const float* be2 = (const float*)d_in[11];
    const float* m2  = (const float*)d_in[12];
    const float* v2  = (const float*)d_in[13];
    const float* Wc  = (const float*)d_in[14];
    const float* bc  = (const float*)d_in[15];
    float* out = (float*)d_out;

    cudaFuncSetAttribute(gemm_hmma<1>, cudaFuncAttributeMaxDynamicSharedMemorySize, SMEM_B);
    cudaFuncSetAttribute(gemm_hmma<2>, cudaFuncAttributeMaxDynamicSharedMemorySize, SMEM_B);

    prep_scales_kernel<<<1, FDIM>>>(b1, g1, be1, m1, v1, b2, g2, be2, m2, v2);
    rowsum_kernel<<<NADJ, 128>>>(w);
    wnorm_kernel<<<(NADJ * NADJ) / 256, 256>>>(w);
    split_d_kernel<<<32768, 256>>>((const float4*)d);
    split_w_kernel<<<1024, 256>>>(W1, 0);
    split_w_kernel<<<1024, 256>>>(W2, 1);
    gemm_hmma<1><<<dim3(4, MROWS / 128), 256, SMEM_B>>>(nullptr);
    gemm_hmma<2><<<dim3(4, MROWS / 128), 256, SMEM_B>>>(Wc);
    gcn_kernel<<<128, 512>>>(bc, out);
}

// round 5
// speedup vs baseline: 2.1641x; 1.0748x over previous
#include <cuda_runtime.h>
#include <cuda_bf16.h>
#include <stdint.h>
#include <math.h>

#define FDIM 512
#define NADJ 512
#define MROWS 65536

// ======================= helpers =======================
__device__ __forceinline__ uint32_t smem_u32(const void* p) {
    uint32_t a;
    asm("{ .reg .u64 t; cvta.to.shared.u64 t, %1; cvt.u32.u64 %0, t; }" : "=r"(a) : "l"(p));
    return a;
}
#define CP_ASYNC16(sa, ga) asm volatile("cp.async.cg.shared.global [%0], [%1], 16;" :: "r"(sa), "l"(ga) : "memory")
#define CP_COMMIT()        asm volatile("cp.async.commit_group;" ::: "memory")
#define CP_WAIT(n)         asm volatile("cp.async.wait_group %0;" :: "n"(n) : "memory")

#define LDSM4(r0, r1, r2, r3, addr) \
    asm volatile("ldmatrix.sync.aligned.m8n8.x4.shared.b16 {%0,%1,%2,%3}, [%4];" \
        : "=r"(r0), "=r"(r1), "=r"(r2), "=r"(r3) : "r"(addr))

#define MMA16816(d, a, b0, b1) \
    asm volatile("mma.sync.aligned.m16n8k16.row.col.f32.bf16.bf16.f32 " \
        "{%0,%1,%2,%3}, {%4,%5,%6,%7}, {%8,%9}, {%0,%1,%2,%3};" \
        : "+f"((d)[0]), "+f"((d)[1]), "+f"((d)[2]), "+f"((d)[3]) \
        : "r"((a)[0]), "r"((a)[1]), "r"((a)[2]), "r"((a)[3]), "r"(b0), "r"(b1))

__device__ __forceinline__ uint32_t pack2(float a, float b) {
    __nv_bfloat162 t = __floats2bfloat162_rn(a, b);
    return *reinterpret_cast<uint32_t*>(&t);
}

// ======================= device scratch =======================
__device__ __nv_bfloat16 g_a2[(size_t)MROWS * 1024];   // d split: [r][0:512)=hi, [512:1024)=lo
__device__ __nv_bfloat16 g_h1s[(size_t)MROWS * 1024];  // h1 split, same layout
__device__ __nv_bfloat16 g_b1s[NADJ * 1536];           // W1: [n][hi|lo|hi]
__device__ __nv_bfloat16 g_b2s[NADJ * 1536];           // W2: [n][hi|lo|hi]
__device__ float g_cpart[4][(size_t)MROWS * 2];
__device__ float g_wnT[NADJ * NADJ];
__device__ float g_dinv[NADJ];
__device__ float g_sb[4 * FDIM];   // s1, t1, s2, t2

// ======================= small prep kernels =======================
// split d (fp32) -> g_a2 (bf16 hi|lo)
__global__ void split_d_kernel(const float4* __restrict__ d) {
    size_t idx = (size_t)blockIdx.x * blockDim.x + threadIdx.x;  // 8388608 float4s
    float4 v = d[idx];
    size_t r = idx >> 7;
    int kq = (int)(idx & 127);
    float hx = __bfloat162float(__float2bfloat16(v.x));
    float hy = __bfloat162float(__float2bfloat16(v.y));
    float hz = __bfloat162float(__float2bfloat16(v.z));
    float hw = __bfloat162float(__float2bfloat16(v.w));
    uint2 hp = make_uint2(pack2(hx, hy), pack2(hz, hw));
    uint2 lp = make_uint2(pack2(v.x - hx, v.y - hy), pack2(v.z - hz, v.w - hw));
    uint2* base = (uint2*)g_a2;
    base[r * 256 + kq]       = hp;
    base[r * 256 + 128 + kq] = lp;
}

__global__ void rowsum_kernel(const float* __restrict__ w) {
    __shared__ float red[128];
    int i = blockIdx.x;
    float s = 0.f;
    for (int j = threadIdx.x; j < NADJ; j += 128) s += w[i * NADJ + j];
    red[threadIdx.x] = s;
    __syncthreads();
    for (int o = 64; o > 0; o >>= 1) {
        if (threadIdx.x < o) red[threadIdx.x] += red[threadIdx.x + o];
        __syncthreads();
    }
    if (threadIdx.x == 0) {
        float di = rsqrtf(red[0] + 1.0f);
        if (isinf(di)) di = 0.f;
        g_dinv[i] = di;
    }
}

__global__ void wnorm_kernel(const float* __restrict__ w) {
    int idx = blockIdx.x * blockDim.x + threadIdx.x;
    int n = idx >> 9, m = idx & 511;
    float a = w[n * NADJ + m] + (n == m ? 1.f : 0.f);
    g_wnT[idx] = a * g_dinv[n] * g_dinv[m];   // wnT[n][m] = w_norm[m][n]
}

// combined: split W1, W2 -> [n][hi|lo|hi]  AND fold BN affine scales
__global__ void prep_all_kernel(const float* __restrict__ W1f, const float* __restrict__ W2f,
                                const float* b1, const float* g1, const float* be1,
                                const float* m1, const float* v1,
                                const float* b2, const float* g2, const float* be2,
                                const float* m2, const float* v2) {
    if (blockIdx.x == 2048) {
        for (int f = threadIdx.x; f < FDIM; f += 256) {
            float s1 = g1[f] * rsqrtf(v1[f] + 1e-5f);
            g_sb[f]        = s1;
            g_sb[FDIM + f] = (b1[f] - m1[f]) * s1 + be1[f];
            float s2 = g2[f] * rsqrtf(v2[f] + 1e-5f);
            g_sb[2*FDIM + f] = s2;
            g_sb[3*FDIM + f] = (b2[f] - m2[f]) * s2 + be2[f];
        }
        return;
    }
    int which = blockIdx.x >= 1024;
    int idx = (blockIdx.x & 1023) * 256 + threadIdx.x;  // 0..262143
    int n = idx >> 9, k = idx & 511;
    const float* W = which ? W2f : W1f;
    float x = W[idx];
    float hf = __bfloat162float(__float2bfloat16(x));
    __nv_bfloat16 h = __float2bfloat16(hf);
    __nv_bfloat16 l = __float2bfloat16(x - hf);
    __nv_bfloat16* out = which ? g_b2s : g_b1s;
    size_t base = (size_t)n * 1536;
    out[base + k] = h;
    out[base + 512 + k] = l;
    out[base + 1024 + k] = h;
}

// ======================= HMMA GEMM =======================
// C[128 x 128] per block. K_eff = 1536 in 48 k-tiles of 32.
// 128 threads = 4 warps as 2(M) x 2(N); warp tile 64x64 via m16n8k16.
// 4-stage cp.async pipeline. smem pitch 80 B (conflict-free ldmatrix phases).
#define KTILES 48
#define PITCH  80
#define HALF_STAGE (128 * PITCH)          // 10240 B (A), same for B
#define STAGE_B (2 * HALF_STAGE)          // 20480 B
#define SMEM_B  (4 * STAGE_B)             // 81920 B

template <int MODE>
__global__ __launch_bounds__(128, 2) void gemm_hmma(const float* __restrict__ Wc) {
    extern __shared__ char dsmem[];
    __shared__ float red[128][2];
    const int tid = threadIdx.x;
    const int wid = tid >> 5;
    const int lane = tid & 31;
    const int bm = blockIdx.y << 7;
    const int bn = blockIdx.x << 7;
    const int moff = (wid & 1) << 6;      // 0 or 64
    const int noff = (wid >> 1) << 6;     // 0 or 64
    const uint32_t sbase = smem_u32(dsmem);

    const __nv_bfloat16* __restrict__ A = (MODE == 1) ? g_a2 : g_h1s;
    const __nv_bfloat16* __restrict__ B = (MODE == 1) ? g_b1s : g_b2s;

    auto issue = [&](int t) {
        const int s = t & 3;
        const int koffA = (t < 32) ? ((t & 15) << 5) : (512 + ((t - 32) << 5));
        const int koffB = t << 5;
        const uint32_t stA = sbase + s * STAGE_B;
        const uint32_t stB = stA + HALF_STAGE;
#pragma unroll
        for (int i = 0; i < 4; i++) {
            const int id = tid + (i << 7);       // 0..511
            const int row = id >> 2, kc = id & 3;
            CP_ASYNC16(stA + row * PITCH + kc * 16, A + (size_t)(bm + row) * 1024 + koffA + kc * 8);
            CP_ASYNC16(stB + row * PITCH + kc * 16, B + (size_t)(bn + row) * 1536 + koffB + kc * 8);
        }
        CP_COMMIT();
    };

    float acc[4][8][4];
#pragma unroll
    for (int i = 0; i < 4; i++)
#pragma unroll
        for (int j = 0; j < 8; j++)
#pragma unroll
            for (int r = 0; r < 4; r++) acc[i][j][r] = 0.f;

    issue(0); issue(1); issue(2);

    // ldmatrix lane addressing
    const int a_row = lane & 15;                 // A: rows m..m+15
    const int a_kb  = ((lane >> 4) & 1) << 4;    // 0 or 16 bytes (k half)
    const int q     = lane >> 3;                 // B quad: 0..3
    const int b_row = ((q >> 1) << 3) + (lane & 7);
    const int b_kb  = (q & 1) << 4;

#pragma unroll 1
    for (int t = 0; t < KTILES; t++) {
        if (t < KTILES - 2)      CP_WAIT(2);
        else if (t == KTILES-2)  CP_WAIT(1);
        else                     CP_WAIT(0);
        __syncthreads();
        if (t + 3 < KTILES) issue(t + 3);

        const uint32_t sA = sbase + (t & 3) * STAGE_B;
        const uint32_t sB = sA + HALF_STAGE;
#pragma unroll
        for (int ks = 0; ks < 2; ks++) {
            uint32_t a[4][4];
            uint32_t b[4][4];
#pragma unroll
            for (int mi = 0; mi < 4; mi++) {
                uint32_t addr = sA + (uint32_t)(moff + mi * 16 + a_row) * PITCH + ks * 32 + a_kb;
                LDSM4(a[mi][0], a[mi][1], a[mi][2], a[mi][3], addr);
            }
#pragma unroll
            for (int p = 0; p < 4; p++) {
                uint32_t addr = sB + (uint32_t)(noff + p * 16 + b_row) * PITCH + ks * 32 + b_kb;
                LDSM4(b[p][0], b[p][1], b[p][2], b[p][3], addr);
            }
#pragma unroll
            for (int mi = 0; mi < 4; mi++) {
#pragma unroll
                for (int ni = 0; ni < 8; ni++) {
                    MMA16816(acc[mi][ni], a[mi], b[ni >> 1][(ni & 1) * 2], b[ni >> 1][(ni & 1) * 2 + 1]);
                }
            }
        }
    }

    // ---------------- epilogue ----------------
    const int row0 = moff + (lane >> 2);         // local row base
    const int col0 = noff + ((lane & 3) << 1);   // local col base (even)

    if (MODE == 1) {
#pragma unroll
        for (int mi = 0; mi < 4; mi++) {
#pragma unroll
            for (int h = 0; h < 2; h++) {
                const size_t r = (size_t)bm + row0 + mi * 16 + h * 8;
#pragma unroll
                for (int ni = 0; ni < 8; ni++) {
                    const int col = bn + col0 + ni * 8;
                    float v0 = fmaf(acc[mi][ni][h * 2],     g_sb[col],     g_sb[FDIM + col]);
                    float v1 = fmaf(acc[mi][ni][h * 2 + 1], g_sb[col + 1], g_sb[FDIM + col + 1]);
                    v0 = v0 > 0.f ? v0 : 0.1f * v0;
                    v1 = v1 > 0.f ? v1 : 0.1f * v1;
                    float h0 = __bfloat162float(__float2bfloat16(v0));
                    float h1 = __bfloat162float(__float2bfloat16(v1));
                    *(uint32_t*)&g_h1s[r * 1024 + col]       = pack2(h0, h1);
                    *(uint32_t*)&g_h1s[r * 1024 + 512 + col] = pack2(v0 - h0, v1 - h1);
                }
            }
        }
    } else {
        __syncthreads();
#pragma unroll
        for (int i = tid; i < 256; i += 128) ((float*)red)[i] = 0.f;
        __syncthreads();
#pragma unroll
        for (int mi = 0; mi < 4; mi++) {
#pragma unroll
            for (int h = 0; h < 2; h++) {
                float p0 = 0.f, p1 = 0.f;
#pragma unroll
                for (int ni = 0; ni < 8; ni++) {
                    const int col = bn + col0 + ni * 8;
                    float v0 = fmaf(acc[mi][ni][h * 2],     g_sb[2*FDIM + col],     g_sb[3*FDIM + col]);
                    float v1 = fmaf(acc[mi][ni][h * 2 + 1], g_sb[2*FDIM + col + 1], g_sb[3*FDIM + col + 1]);
                    v0 = v0 > 0.f ? v0 : 0.1f * v0;
                    v1 = v1 > 0.f ? v1 : 0.1f * v1;
                    p0 = fmaf(v0, Wc[col], p0);        p0 = fmaf(v1, Wc[col + 1], p0);
                    p1 = fmaf(v0, Wc[FDIM + col], p1); p1 = fmaf(v1, Wc[FDIM + col + 1], p1);
                }
                // reduce across the 4 lanes sharing this row (lane&3 varies)
                p0 += __shfl_xor_sync(0xFFFFFFFF, p0, 1); p0 += __shfl_xor_sync(0xFFFFFFFF, p0, 2);
                p1 += __shfl_xor_sync(0xFFFFFFFF, p1, 1); p1 += __shfl_xor_sync(0xFFFFFFFF, p1, 2);
                if ((lane & 3) == 0) {
                    const int rl = row0 + mi * 16 + h * 8;
                    atomicAdd(&red[rl][0], p0);
                    atomicAdd(&red[rl][1], p1);
                }
            }
        }
        __syncthreads();
        {
            const int rl = tid;
            g_cpart[blockIdx.x][((size_t)bm + rl) * 2]     = red[rl][0];
            g_cpart[blockIdx.x][((size_t)bm + rl) * 2 + 1] = red[rl][1];
        }
    }
}

// ======================= GCN propagation + bias =======================
__global__ __launch_bounds__(512) void gcn_kernel(const float* __restrict__ bc,
                                                  float* __restrict__ out) {
    __shared__ float2 cs[NADJ];
    int b = blockIdx.x;
    int t = threadIdx.x;
    {
        float2 v = make_float2(0.f, 0.f);
        size_t base = (size_t)b * (NADJ * 2) + t * 2;
#pragma unroll
        for (int nb = 0; nb < 4; nb++) {
            v.x += g_cpart[nb][base];
            v.y += g_cpart[nb][base + 1];
        }
        cs[t] = v;
    }
    __syncthreads();
    float a0 = bc[0], a1 = bc[1];
    const float4* wr4 = (const float4*)(g_wnT + (size_t)t * NADJ);
#pragma unroll 4
    for (int m4 = 0; m4 < NADJ / 4; m4++) {
        float4 wv = wr4[m4];
        float2 c0 = cs[m4*4+0], c1 = cs[m4*4+1], c2 = cs[m4*4+2], c3 = cs[m4*4+3];
        a0 = fmaf(wv.x, c0.x, a0); a1 = fmaf(wv.x, c0.y, a1);
        a0 = fmaf(wv.y, c1.x, a0); a1 = fmaf(wv.y, c1.y, a1);
        a0 = fmaf(wv.z, c2.x, a0); a1 = fmaf(wv.z, c2.y, a1);
        a0 = fmaf(wv.w, c3.x, a0); a1 = fmaf(wv.w, c3.y, a1);
    }
    size_t o = ((size_t)b * NADJ + t) * 2;
    out[o]     = a0;
    out[o + 1] = a1;
}

// ======================= launch =======================
extern "C" void kernel_launch(void* const* d_in, const int* in_sizes, int n_in,
                              void* d_out, int out_size) {
    const float* d   = (const float*)d_in[0];
    const float* w   = (const float*)d_in[1];
    const float* W1  = (const float*)d_in[2];
    const float* b1  = (const float*)d_in[3];
    const float* g1  = (const float*)d_in[4];
    const float* be1 = (const float*)d_in[5];
    const float* m1  = (const float*)d_in[6];
    const float* v1  = (const float*)d_in[7];
    const float* W2  = (const float*)d_in[8];
    const float* b2  = (const float*)d_in[9];
    const float* g2  = (const float*)d_in[10];
    const float* be2 = (const float*)d_in[11];
    const float* m2  = (const float*)d_in[12];
    const float* v2  = (const float*)d_in[13];
    const float* Wc  = (const float*)d_in[14];
    const float* bc  = (const float*)d_in[15];
    float* out = (float*)d_out;

    cudaFuncSetAttribute(gemm_hmma<1>, cudaFuncAttributeMaxDynamicSharedMemorySize, SMEM_B);
    cudaFuncSetAttribute(gemm_hmma<2>, cudaFuncAttributeMaxDynamicSharedMemorySize, SMEM_B);

    split_d_kernel<<<32768, 256>>>((const float4*)d);
    rowsum_kernel<<<NADJ, 128>>>(w);
    wnorm_kernel<<<(NADJ * NADJ) / 256, 256>>>(w);
    prep_all_kernel<<<2049, 256>>>(W1, W2, b1, g1, be1, m1, v1, b2, g2, be2, m2, v2);
    gemm_hmma<1><<<dim3(4, MROWS / 128), 128, SMEM_B>>>(nullptr);
    gemm_hmma<2><<<dim3(4, MROWS / 128), 128, SMEM_B>>>(Wc);
    gcn_kernel<<<128, 512>>>(bc, out);
}

// round 7
// speedup vs baseline: 2.8265x; 1.3061x over previous
#include <cuda_runtime.h>
#include <cuda_fp16.h>
#include <stdint.h>
#include <math.h>

#define FDIM 512
#define NADJ 512
#define MROWS 65536

// ======================= helpers =======================
__device__ __forceinline__ uint32_t smem_u32(const void* p) {
    uint32_t a;
    asm("{ .reg .u64 t; cvta.to.shared.u64 t, %1; cvt.u32.u64 %0, t; }" : "=r"(a) : "l"(p));
    return a;
}
#define CP_ASYNC16(sa, ga) asm volatile("cp.async.cg.shared.global [%0], [%1], 16;" :: "r"(sa), "l"(ga) : "memory")
#define CP_COMMIT()        asm volatile("cp.async.commit_group;" ::: "memory")
#define CP_WAIT(n)         asm volatile("cp.async.wait_group %0;" :: "n"(n) : "memory")

#define LDSM4(r0, r1, r2, r3, addr) \
    asm volatile("ldmatrix.sync.aligned.m8n8.x4.shared.b16 {%0,%1,%2,%3}, [%4];" \
        : "=r"(r0), "=r"(r1), "=r"(r2), "=r"(r3) : "r"(addr))

#define MMA16816(d, a, b0, b1) \
    asm volatile("mma.sync.aligned.m16n8k16.row.col.f32.f16.f16.f32 " \
        "{%0,%1,%2,%3}, {%4,%5,%6,%7}, {%8,%9}, {%0,%1,%2,%3};" \
        : "+f"((d)[0]), "+f"((d)[1]), "+f"((d)[2]), "+f"((d)[3]) \
        : "r"((a)[0]), "r"((a)[1]), "r"((a)[2]), "r"((a)[3]), "r"(b0), "r"(b1))

__device__ __forceinline__ uint32_t pack2h(float a, float b) {
    __half2 t = __floats2half2_rn(a, b);
    return *reinterpret_cast<uint32_t*>(&t);
}

// ======================= device scratch =======================
__device__ __half g_a2[(size_t)MROWS * 1024];   // d split: [r][0:512)=hi, [512:1024)=lo (fp16)
__device__ __half g_h1s[(size_t)MROWS * 1024];  // h1 split, same layout
__device__ __half g_b1s[NADJ * 512];            // W1 hi (fp16)
__device__ __half g_b2s[NADJ * 512];            // W2 hi (fp16)
__device__ float g_cpart[4][(size_t)MROWS * 2];
__device__ float g_wnT[NADJ * NADJ];
__device__ float g_dinv[NADJ];
__device__ float g_sb[4 * FDIM];   // s1, t1, s2, t2

// ======================= small prep kernels =======================
// split d (fp32) -> g_a2 (fp16 hi|lo, exact 2-term split)
__global__ void split_d_kernel(const float4* __restrict__ d) {
    size_t idx = (size_t)blockIdx.x * blockDim.x + threadIdx.x;  // 8388608 float4s
    float4 v = d[idx];
    size_t r = idx >> 7;
    int kq = (int)(idx & 127);
    float hx = __half2float(__float2half(v.x));
    float hy = __half2float(__float2half(v.y));
    float hz = __half2float(__float2half(v.z));
    float hw = __half2float(__float2half(v.w));
    uint2 hp = make_uint2(pack2h(hx, hy), pack2h(hz, hw));
    uint2 lp = make_uint2(pack2h(v.x - hx, v.y - hy), pack2h(v.z - hz, v.w - hw));
    uint2* base = (uint2*)g_a2;
    base[r * 256 + kq]       = hp;
    base[r * 256 + 128 + kq] = lp;
}

__global__ void rowsum_kernel(const float* __restrict__ w) {
    __shared__ float red[128];
    int i = blockIdx.x;
    float s = 0.f;
    for (int j = threadIdx.x; j < NADJ; j += 128) s += w[i * NADJ + j];
    red[threadIdx.x] = s;
    __syncthreads();
    for (int o = 64; o > 0; o >>= 1) {
        if (threadIdx.x < o) red[threadIdx.x] += red[threadIdx.x + o];
        __syncthreads();
    }
    if (threadIdx.x == 0) {
        float di = rsqrtf(red[0] + 1.0f);
        if (isinf(di)) di = 0.f;
        g_dinv[i] = di;
    }
}

__global__ void wnorm_kernel(const float* __restrict__ w) {
    int idx = blockIdx.x * blockDim.x + threadIdx.x;
    int n = idx >> 9, m = idx & 511;
    float a = w[n * NADJ + m] + (n == m ? 1.f : 0.f);
    g_wnT[idx] = a * g_dinv[n] * g_dinv[m];   // wnT[n][m] = w_norm[m][n]
}

// combined: W1, W2 -> fp16 hi  AND fold BN affine scales
__global__ void prep_all_kernel(const float* __restrict__ W1f, const float* __restrict__ W2f,
                                const float* b1, const float* g1, const float* be1,
                                const float* m1, const float* v1,
                                const float* b2, const float* g2, const float* be2,
                                const float* m2, const float* v2) {
    if (blockIdx.x == 2048) {
        for (int f = threadIdx.x; f < FDIM; f += 256) {
            float s1 = g1[f] * rsqrtf(v1[f] + 1e-5f);
            g_sb[f]        = s1;
            g_sb[FDIM + f] = (b1[f] - m1[f]) * s1 + be1[f];
            float s2 = g2[f] * rsqrtf(v2[f] + 1e-5f);
            g_sb[2*FDIM + f] = s2;
            g_sb[3*FDIM + f] = (b2[f] - m2[f]) * s2 + be2[f];
        }
        return;
    }
    int which = blockIdx.x >= 1024;
    int idx = (blockIdx.x & 1023) * 256 + threadIdx.x;  // 0..262143
    const float* W = which ? W2f : W1f;
    __half* out = which ? g_b2s : g_b1s;
    out[idx] = __float2half(W[idx]);
}

// ======================= HMMA GEMM (fp16, 2-term) =======================
// C[128 x 128] per block. K_eff = 1024 in 32 k-tiles of 32.
// A = [Ah | Al], B hi reused for both segments (koffB wraps at 512).
// 128 threads = 4 warps as 2(M) x 2(N); warp tile 64x64 via m16n8k16.
// 4-stage cp.async pipeline. smem pitch 80 B (conflict-free ldmatrix phases).
#define KTILES 32
#define PITCH  80
#define HALF_STAGE (128 * PITCH)          // 10240 B (A), same for B
#define STAGE_B (2 * HALF_STAGE)          // 20480 B
#define SMEM_B  (4 * STAGE_B)             // 81920 B

template <int MODE>
__global__ __launch_bounds__(128, 2) void gemm_hmma(const float* __restrict__ Wc) {
    extern __shared__ char dsmem[];
    __shared__ float red[128][2];
    const int tid = threadIdx.x;
    const int wid = tid >> 5;
    const int lane = tid & 31;
    const int bm = blockIdx.y << 7;
    const int bn = blockIdx.x << 7;
    const int moff = (wid & 1) << 6;      // 0 or 64
    const int noff = (wid >> 1) << 6;     // 0 or 64
    const uint32_t sbase = smem_u32(dsmem);

    const __half* __restrict__ A = (MODE == 1) ? g_a2 : g_h1s;
    const __half* __restrict__ B = (MODE == 1) ? g_b1s : g_b2s;

    auto issue = [&](int t) {
        const int s = t & 3;
        const int koffA = t << 5;             // 0..992 over [hi|lo]
        const int koffB = (t & 15) << 5;      // B hi reused for both segments
        const uint32_t stA = sbase + s * STAGE_B;
        const uint32_t stB = stA + HALF_STAGE;
#pragma unroll
        for (int i = 0; i < 4; i++) {
            const int id = tid + (i << 7);       // 0..511
            const int row = id >> 2, kc = id & 3;
            CP_ASYNC16(stA + row * PITCH + kc * 16, A + (size_t)(bm + row) * 1024 + koffA + kc * 8);
            CP_ASYNC16(stB + row * PITCH + kc * 16, B + (size_t)(bn + row) * 512 + koffB + kc * 8);
        }
        CP_COMMIT();
    };

    float acc[4][8][4];
#pragma unroll
    for (int i = 0; i < 4; i++)
#pragma unroll
        for (int j = 0; j < 8; j++)
#pragma unroll
            for (int r = 0; r < 4; r++) acc[i][j][r] = 0.f;

    issue(0); issue(1); issue(2);

    // ldmatrix lane addressing
    const int a_row = lane & 15;                 // A: rows m..m+15
    const int a_kb  = ((lane >> 4) & 1) << 4;    // 0 or 16 bytes (k half)
    const int q     = lane >> 3;                 // B quad: 0..3
    const int b_row = ((q >> 1) << 3) + (lane & 7);
    const int b_kb  = (q & 1) << 4;

#pragma unroll 1
    for (int t = 0; t < KTILES; t++) {
        if (t < KTILES - 2)      CP_WAIT(2);
        else if (t == KTILES-2)  CP_WAIT(1);
        else                     CP_WAIT(0);
        __syncthreads();
        if (t + 3 < KTILES) issue(t + 3);

        const uint32_t sA = sbase + (t & 3) * STAGE_B;
        const uint32_t sB = sA + HALF_STAGE;
#pragma unroll
        for (int ks = 0; ks < 2; ks++) {
            uint32_t a[4][4];
            uint32_t b[4][4];
#pragma unroll
            for (int mi = 0; mi < 4; mi++) {
                uint32_t addr = sA + (uint32_t)(moff + mi * 16 + a_row) * PITCH + ks * 32 + a_kb;
                LDSM4(a[mi][0], a[mi][1], a[mi][2], a[mi][3], addr);
            }
#pragma unroll
            for (int p = 0; p < 4; p++) {
                uint32_t addr = sB + (uint32_t)(noff + p * 16 + b_row) * PITCH + ks * 32 + b_kb;
                LDSM4(b[p][0], b[p][1], b[p][2], b[p][3], addr);
            }
#pragma unroll
            for (int mi = 0; mi < 4; mi++) {
#pragma unroll
                for (int ni = 0; ni < 8; ni++) {
                    MMA16816(acc[mi][ni], a[mi], b[ni >> 1][(ni & 1) * 2], b[ni >> 1][(ni & 1) * 2 + 1]);
                }
            }
        }
    }

    // ---------------- epilogue ----------------
    const int row0 = moff + (lane >> 2);         // local row base
    const int col0 = noff + ((lane & 3) << 1);   // local col base (even)

    if (MODE == 1) {
#pragma unroll
        for (int mi = 0; mi < 4; mi++) {
#pragma unroll
            for (int h = 0; h < 2; h++) {
                const size_t r = (size_t)bm + row0 + mi * 16 + h * 8;
#pragma unroll
                for (int ni = 0; ni < 8; ni++) {
                    const int col = bn + col0 + ni * 8;
                    float v0 = fmaf(acc[mi][ni][h * 2],     g_sb[col],     g_sb[FDIM + col]);
                    float v1 = fmaf(acc[mi][ni][h * 2 + 1], g_sb[col + 1], g_sb[FDIM + col + 1]);
                    v0 = v0 > 0.f ? v0 : 0.1f * v0;
                    v1 = v1 > 0.f ? v1 : 0.1f * v1;
                    float h0 = __half2float(__float2half(v0));
                    float h1 = __half2float(__float2half(v1));
                    *(uint32_t*)&g_h1s[r * 1024 + col]       = pack2h(h0, h1);
                    *(uint32_t*)&g_h1s[r * 1024 + 512 + col] = pack2h(v0 - h0, v1 - h1);
                }
            }
        }
    } else {
        __syncthreads();
#pragma unroll
        for (int i = tid; i < 256; i += 128) ((float*)red)[i] = 0.f;
        __syncthreads();
#pragma unroll
        for (int mi = 0; mi < 4; mi++) {
#pragma unroll
            for (int h = 0; h < 2; h++) {
                float p0 = 0.f, p1 = 0.f;
#pragma unroll
                for (int ni = 0; ni < 8; ni++) {
                    const int col = bn + col0 + ni * 8;
                    float v0 = fmaf(acc[mi][ni][h * 2],     g_sb[2*FDIM + col],     g_sb[3*FDIM + col]);
                    float v1 = fmaf(acc[mi][ni][h * 2 + 1], g_sb[2*FDIM + col + 1], g_sb[3*FDIM + col + 1]);
                    v0 = v0 > 0.f ? v0 : 0.1f * v0;
                    v1 = v1 > 0.f ? v1 : 0.1f * v1;
                    p0 = fmaf(v0, Wc[col], p0);        p0 = fmaf(v1, Wc[col + 1], p0);
                    p1 = fmaf(v0, Wc[FDIM + col], p1); p1 = fmaf(v1, Wc[FDIM + col + 1], p1);
                }
                // reduce across the 4 lanes sharing this row (lane&3 varies)
                p0 += __shfl_xor_sync(0xFFFFFFFF, p0, 1); p0 += __shfl_xor_sync(0xFFFFFFFF, p0, 2);
                p1 += __shfl_xor_sync(0xFFFFFFFF, p1, 1); p1 += __shfl_xor_sync(0xFFFFFFFF, p1, 2);
                if ((lane & 3) == 0) {
                    const int rl = row0 + mi * 16 + h * 8;
                    atomicAdd(&red[rl][0], p0);
                    atomicAdd(&red[rl][1], p1);
                }
            }
        }
        __syncthreads();
        {
            const int rl = tid;
            g_cpart[blockIdx.x][((size_t)bm + rl) * 2]     = red[rl][0];
            g_cpart[blockIdx.x][((size_t)bm + rl) * 2 + 1] = red[rl][1];
        }
    }
}

// ======================= GCN propagation + bias =======================
__global__ __launch_bounds__(512) void gcn_kernel(const float* __restrict__ bc,
                                                  float* __restrict__ out) {
    __shared__ float2 cs[NADJ];
    int b = blockIdx.x;
    int t = threadIdx.x;
    {
        float2 v = make_float2(0.f, 0.f);
        size_t base = (size_t)b * (NADJ * 2) + t * 2;
#pragma unroll
        for (int nb = 0; nb < 4; nb++) {
            v.x += g_cpart[nb][base];
            v.y += g_cpart[nb][base + 1];
        }
        cs[t] = v;
    }
    __syncthreads();
    float a0 = bc[0], a1 = bc[1];
    const float4* wr4 = (const float4*)(g_wnT + (size_t)t * NADJ);
#pragma unroll 4
    for (int m4 = 0; m4 < NADJ / 4; m4++) {
        float4 wv = wr4[m4];
        float2 c0 = cs[m4*4+0], c1 = cs[m4*4+1], c2 = cs[m4*4+2], c3 = cs[m4*4+3];
        a0 = fmaf(wv.x, c0.x, a0); a1 = fmaf(wv.x, c0.y, a1);
        a0 = fmaf(wv.y, c1.x, a0); a1 = fmaf(wv.y, c1.y, a1);
        a0 = fmaf(wv.z, c2.x, a0); a1 = fmaf(wv.z, c2.y, a1);
        a0 = fmaf(wv.w, c3.x, a0); a1 = fmaf(wv.w, c3.y, a1);
    }
    size_t o = ((size_t)b * NADJ + t) * 2;
    out[o]     = a0;
    out[o + 1] = a1;
}

// ======================= launch =======================
extern "C" void kernel_launch(void* const* d_in, const int* in_sizes, int n_in,
                              void* d_out, int out_size) {
    const float* d   = (const float*)d_in[0];
    const float* w   = (const float*)d_in[1];
    const float* W1  = (const float*)d_in[2];
    const float* b1  = (const float*)d_in[3];
    const float* g1  = (const float*)d_in[4];
    const float* be1 = (const float*)d_in[5];
    const float* m1  = (const float*)d_in[6];
    const float* v1  = (const float*)d_in[7];
    const float* W2  = (const float*)d_in[8];
    const float* b2  = (const float*)d_in[9];
    const float* g2  = (const float*)d_in[10];
    const float* be2 = (const float*)d_in[11];
    const float* m2  = (const float*)d_in[12];
    const float* v2  = (const float*)d_in[13];
    const float* Wc  = (const float*)d_in[14];
    const float* bc  = (const float*)d_in[15];
    float* out = (float*)d_out;

    cudaFuncSetAttribute(gemm_hmma<1>, cudaFuncAttributeMaxDynamicSharedMemorySize, SMEM_B);
    cudaFuncSetAttribute(gemm_hmma<2>, cudaFuncAttributeMaxDynamicSharedMemorySize, SMEM_B);

    split_d_kernel<<<32768, 256>>>((const float4*)d);
    rowsum_kernel<<<NADJ, 128>>>(w);
    wnorm_kernel<<<(NADJ * NADJ) / 256, 256>>>(w);
    prep_all_kernel<<<2049, 256>>>(W1, W2, b1, g1, be1, m1, v1, b2, g2, be2, m2, v2);
    gemm_hmma<1><<<dim3(4, MROWS / 128), 128, SMEM_B>>>(nullptr);
    gemm_hmma<2><<<dim3(4, MROWS / 128), 128, SMEM_B>>>(Wc);
    gcn_kernel<<<128, 512>>>(bc, out);
}

// round 8
// speedup vs baseline: 4.4316x; 1.5679x over previous
#include <cuda_runtime.h>
#include <cuda_fp16.h>
#include <stdint.h>
#include <math.h>

#define FDIM 512
#define NADJ 512
#define MROWS 65536

// ======================= helpers =======================
__device__ __forceinline__ uint32_t smem_u32(const void* p) {
    uint32_t a;
    asm("{ .reg .u64 t; cvta.to.shared.u64 t, %1; cvt.u32.u64 %0, t; }" : "=r"(a) : "l"(p));
    return a;
}
#define CP_ASYNC16(sa, ga) asm volatile("cp.async.cg.shared.global [%0], [%1], 16;" :: "r"(sa), "l"(ga) : "memory")
#define CP_COMMIT()        asm volatile("cp.async.commit_group;" ::: "memory")
#define CP_WAIT(n)         asm volatile("cp.async.wait_group %0;" :: "n"(n) : "memory")

#define LDSM4(r0, r1, r2, r3, addr) \
    asm volatile("ldmatrix.sync.aligned.m8n8.x4.shared.b16 {%0,%1,%2,%3}, [%4];" \
        : "=r"(r0), "=r"(r1), "=r"(r2), "=r"(r3) : "r"(addr))

#define MMA16816(d, a, b0, b1) \
    asm volatile("mma.sync.aligned.m16n8k16.row.col.f32.f16.f16.f32 " \
        "{%0,%1,%2,%3}, {%4,%5,%6,%7}, {%8,%9}, {%0,%1,%2,%3};" \
        : "+f"((d)[0]), "+f"((d)[1]), "+f"((d)[2]), "+f"((d)[3]) \
        : "r"((a)[0]), "r"((a)[1]), "r"((a)[2]), "r"((a)[3]), "r"(b0), "r"(b1))

__device__ __forceinline__ uint32_t pack2h(float a, float b) {
    __half2 t = __floats2half2_rn(a, b);
    return *reinterpret_cast<uint32_t*>(&t);
}

// ======================= device scratch =======================
__device__ __half g_a2[(size_t)MROWS * 512];    // d as fp16
__device__ __half g_h1s[(size_t)MROWS * 512];   // h1 as fp16
__device__ __half g_b1s[NADJ * 512];            // W1 fp16
__device__ __half g_b2s[NADJ * 512];            // W2 fp16
__device__ float g_cpart[4][(size_t)MROWS * 2];
__device__ float g_wnT[NADJ * NADJ];
__device__ float g_dinv[NADJ];
__device__ float g_sb[4 * FDIM];   // s1, t1, s2, t2

// ======================= small prep kernels =======================
// convert d (fp32) -> g_a2 (fp16)
__global__ void split_d_kernel(const float4* __restrict__ d) {
    size_t idx = (size_t)blockIdx.x * blockDim.x + threadIdx.x;  // 8388608 float4s
    float4 v = d[idx];
    ((uint2*)g_a2)[idx] = make_uint2(pack2h(v.x, v.y), pack2h(v.z, v.w));
}

__global__ void rowsum_kernel(const float* __restrict__ w) {
    __shared__ float red[128];
    int i = blockIdx.x;
    float s = 0.f;
    for (int j = threadIdx.x; j < NADJ; j += 128) s += w[i * NADJ + j];
    red[threadIdx.x] = s;
    __syncthreads();
    for (int o = 64; o > 0; o >>= 1) {
        if (threadIdx.x < o) red[threadIdx.x] += red[threadIdx.x + o];
        __syncthreads();
    }
    if (threadIdx.x == 0) {
        float di = rsqrtf(red[0] + 1.0f);
        if (isinf(di)) di = 0.f;
        g_dinv[i] = di;
    }
}

__global__ void wnorm_kernel(const float* __restrict__ w) {
    int idx = blockIdx.x * blockDim.x + threadIdx.x;
    int n = idx >> 9, m = idx & 511;
    float a = w[n * NADJ + m] + (n == m ? 1.f : 0.f);
    g_wnT[idx] = a * g_dinv[n] * g_dinv[m];   // wnT[n][m] = w_norm[m][n]
}

// combined: W1, W2 -> fp16  AND fold BN affine scales
__global__ void prep_all_kernel(const float* __restrict__ W1f, const float* __restrict__ W2f,
                                const float* b1, const float* g1, const float* be1,
                                const float* m1, const float* v1,
                                const float* b2, const float* g2, const float* be2,
                                const float* m2, const float* v2) {
    if (blockIdx.x == 2048) {
        for (int f = threadIdx.x; f < FDIM; f += 256) {
            float s1 = g1[f] * rsqrtf(v1[f] + 1e-5f);
            g_sb[f]        = s1;
            g_sb[FDIM + f] = (b1[f] - m1[f]) * s1 + be1[f];
            float s2 = g2[f] * rsqrtf(v2[f] + 1e-5f);
            g_sb[2*FDIM + f] = s2;
            g_sb[3*FDIM + f] = (b2[f] - m2[f]) * s2 + be2[f];
        }
        return;
    }
    int which = blockIdx.x >= 1024;
    int idx = (blockIdx.x & 1023) * 256 + threadIdx.x;  // 0..262143
    const float* W = which ? W2f : W1f;
    __half* out = which ? g_b2s : g_b1s;
    out[idx] = __float2half(W[idx]);
}

// ======================= HMMA GEMM (pure fp16) =======================
// C[128 x 128] per block. K = 512 in 16 k-tiles of 32.
// 128 threads = 4 warps as 2(M) x 2(N); warp tile 64x64 via m16n8k16.
// 4-stage cp.async pipeline. smem pitch 80 B (conflict-free ldmatrix phases).
#define KTILES 16
#define PITCH  80
#define HALF_STAGE (128 * PITCH)          // 10240 B (A), same for B
#define STAGE_B (2 * HALF_STAGE)          // 20480 B
#define SMEM_B  (4 * STAGE_B)             // 81920 B

template <int MODE>
__global__ __launch_bounds__(128, 2) void gemm_hmma(const float* __restrict__ Wc) {
    extern __shared__ char dsmem[];
    __shared__ float red[128][2];
    const int tid = threadIdx.x;
    const int wid = tid >> 5;
    const int lane = tid & 31;
    const int bm = blockIdx.y << 7;
    const int bn = blockIdx.x << 7;
    const int moff = (wid & 1) << 6;      // 0 or 64
    const int noff = (wid >> 1) << 6;     // 0 or 64
    const uint32_t sbase = smem_u32(dsmem);

    const __half* __restrict__ A = (MODE == 1) ? g_a2 : g_h1s;
    const __half* __restrict__ B = (MODE == 1) ? g_b1s : g_b2s;

    auto issue = [&](int t) {
        const int s = t & 3;
        const int koff = t << 5;
        const uint32_t stA = sbase + s * STAGE_B;
        const uint32_t stB = stA + HALF_STAGE;
#pragma unroll
        for (int i = 0; i < 4; i++) {
            const int id = tid + (i << 7);       // 0..511
            const int row = id >> 2, kc = id & 3;
            CP_ASYNC16(stA + row * PITCH + kc * 16, A + (size_t)(bm + row) * 512 + koff + kc * 8);
            CP_ASYNC16(stB + row * PITCH + kc * 16, B + (size_t)(bn + row) * 512 + koff + kc * 8);
        }
        CP_COMMIT();
    };

    float acc[4][8][4];
#pragma unroll
    for (int i = 0; i < 4; i++)
#pragma unroll
        for (int j = 0; j < 8; j++)
#pragma unroll
            for (int r = 0; r < 4; r++) acc[i][j][r] = 0.f;

    issue(0); issue(1); issue(2);

    // ldmatrix lane addressing
    const int a_row = lane & 15;                 // A: rows m..m+15
    const int a_kb  = ((lane >> 4) & 1) << 4;    // 0 or 16 bytes (k half)
    const int q     = lane >> 3;                 // B quad: 0..3
    const int b_row = ((q >> 1) << 3) + (lane & 7);
    const int b_kb  = (q & 1) << 4;

#pragma unroll 1
    for (int t = 0; t < KTILES; t++) {
        if (t < KTILES - 2)      CP_WAIT(2);
        else if (t == KTILES-2)  CP_WAIT(1);
        else                     CP_WAIT(0);
        __syncthreads();
        if (t + 3 < KTILES) issue(t + 3);

        const uint32_t sA = sbase + (t & 3) * STAGE_B;
        const uint32_t sB = sA + HALF_STAGE;
#pragma unroll
        for (int ks = 0; ks < 2; ks++) {
            uint32_t a[4][4];
            uint32_t b[4][4];
#pragma unroll
            for (int mi = 0; mi < 4; mi++) {
                uint32_t addr = sA + (uint32_t)(moff + mi * 16 + a_row) * PITCH + ks * 32 + a_kb;
                LDSM4(a[mi][0], a[mi][1], a[mi][2], a[mi][3], addr);
            }
#pragma unroll
            for (int p = 0; p < 4; p++) {
                uint32_t addr = sB + (uint32_t)(noff + p * 16 + b_row) * PITCH + ks * 32 + b_kb;
                LDSM4(b[p][0], b[p][1], b[p][2], b[p][3], addr);
            }
#pragma unroll
            for (int mi = 0; mi < 4; mi++) {
#pragma unroll
                for (int ni = 0; ni < 8; ni++) {
                    MMA16816(acc[mi][ni], a[mi], b[ni >> 1][(ni & 1) * 2], b[ni >> 1][(ni & 1) * 2 + 1]);
                }
            }
        }
    }

    // ---------------- epilogue ----------------
    const int row0 = moff + (lane >> 2);         // local row base
    const int col0 = noff + ((lane & 3) << 1);   // local col base (even)

    if (MODE == 1) {
#pragma unroll
        for (int mi = 0; mi < 4; mi++) {
#pragma unroll
            for (int h = 0; h < 2; h++) {
                const size_t r = (size_t)bm + row0 + mi * 16 + h * 8;
#pragma unroll
                for (int ni = 0; ni < 8; ni++) {
                    const int col = bn + col0 + ni * 8;
                    float v0 = fmaf(acc[mi][ni][h * 2],     g_sb[col],     g_sb[FDIM + col]);
                    float v1 = fmaf(acc[mi][ni][h * 2 + 1], g_sb[col + 1], g_sb[FDIM + col + 1]);
                    v0 = v0 > 0.f ? v0 : 0.1f * v0;
                    v1 = v1 > 0.f ? v1 : 0.1f * v1;
                    *(uint32_t*)&g_h1s[r * 512 + col] = pack2h(v0, v1);
                }
            }
        }
    } else {
        __syncthreads();
#pragma unroll
        for (int i = tid; i < 256; i += 128) ((float*)red)[i] = 0.f;
        __syncthreads();
#pragma unroll
        for (int mi = 0; mi < 4; mi++) {
#pragma unroll
            for (int h = 0; h < 2; h++) {
                float p0 = 0.f, p1 = 0.f;
#pragma unroll
                for (int ni = 0; ni < 8; ni++) {
                    const int col = bn + col0 + ni * 8;
                    float v0 = fmaf(acc[mi][ni][h * 2],     g_sb[2*FDIM + col],     g_sb[3*FDIM + col]);
                    float v1 = fmaf(acc[mi][ni][h * 2 + 1], g_sb[2*FDIM + col + 1], g_sb[3*FDIM + col + 1]);
                    v0 = v0 > 0.f ? v0 : 0.1f * v0;
                    v1 = v1 > 0.f ? v1 : 0.1f * v1;
                    p0 = fmaf(v0, Wc[col], p0);        p0 = fmaf(v1, Wc[col + 1], p0);
                    p1 = fmaf(v0, Wc[FDIM + col], p1); p1 = fmaf(v1, Wc[FDIM + col + 1], p1);
                }
                // reduce across the 4 lanes sharing this row (lane&3 varies)
                p0 += __shfl_xor_sync(0xFFFFFFFF, p0, 1); p0 += __shfl_xor_sync(0xFFFFFFFF, p0, 2);
                p1 += __shfl_xor_sync(0xFFFFFFFF, p1, 1); p1 += __shfl_xor_sync(0xFFFFFFFF, p1, 2);
                if ((lane & 3) == 0) {
                    const int rl = row0 + mi * 16 + h * 8;
                    atomicAdd(&red[rl][0], p0);
                    atomicAdd(&red[rl][1], p1);
                }
            }
        }
        __syncthreads();
        {
            const int rl = tid;
            g_cpart[blockIdx.x][((size_t)bm + rl) * 2]     = red[rl][0];
            g_cpart[blockIdx.x][((size_t)bm + rl) * 2 + 1] = red[rl][1];
        }
    }
}

// ======================= GCN propagation + bias =======================
__global__ __launch_bounds__(512) void gcn_kernel(const float* __restrict__ bc,
                                                  float* __restrict__ out) {
    __shared__ float2 cs[NADJ];
    int b = blockIdx.x;
    int t = threadIdx.x;
    {
        float2 v = make_float2(0.f, 0.f);
        size_t base = (size_t)b * (NADJ * 2) + t * 2;
#pragma unroll
        for (int nb = 0; nb < 4; nb++) {
            v.x += g_cpart[nb][base];
            v.y += g_cpart[nb][base + 1];
        }
        cs[t] = v;
    }
    __syncthreads();
    float a0 = bc[0], a1 = bc[1];
    const float4* wr4 = (const float4*)(g_wnT + (size_t)t * NADJ);
#pragma unroll 4
    for (int m4 = 0; m4 < NADJ / 4; m4++) {
        float4 wv = wr4[m4];
        float2 c0 = cs[m4*4+0], c1 = cs[m4*4+1], c2 = cs[m4*4+2], c3 = cs[m4*4+3];
        a0 = fmaf(wv.x, c0.x, a0); a1 = fmaf(wv.x, c0.y, a1);
        a0 = fmaf(wv.y, c1.x, a0); a1 = fmaf(wv.y, c1.y, a1);
        a0 = fmaf(wv.z, c2.x, a0); a1 = fmaf(wv.z, c2.y, a1);
        a0 = fmaf(wv.w, c3.x, a0); a1 = fmaf(wv.w, c3.y, a1);
    }
    size_t o = ((size_t)b * NADJ + t) * 2;
    out[o]     = a0;
    out[o + 1] = a1;
}

// ======================= launch =======================
extern "C" void kernel_launch(void* const* d_in, const int* in_sizes, int n_in,
                              void* d_out, int out_size) {
    const float* d   = (const float*)d_in[0];
    const float* w   = (const float*)d_in[1];
    const float* W1  = (const float*)d_in[2];
    const float* b1  = (const float*)d_in[3];
    const float* g1  = (const float*)d_in[4];
    const float* be1 = (const float*)d_in[5];
    const float* m1  = (const float*)d_in[6];
    const float* v1  = (const float*)d_in[7];
    const float* W2  = (const float*)d_in[8];
    const float* b2  = (const float*)d_in[9];
    const float* g2  = (const float*)d_in[10];
    const float* be2 = (const float*)d_in[11];
    const float* m2  = (const float*)d_in[12];
    const float* v2  = (const float*)d_in[13];
    const float* Wc  = (const float*)d_in[14];
    const float* bc  = (const float*)d_in[15];
    float* out = (float*)d_out;

    cudaFuncSetAttribute(gemm_hmma<1>, cudaFuncAttributeMaxDynamicSharedMemorySize, SMEM_B);
    cudaFuncSetAttribute(gemm_hmma<2>, cudaFuncAttributeMaxDynamicSharedMemorySize, SMEM_B);

    split_d_kernel<<<32768, 256>>>((const float4*)d);
    rowsum_kernel<<<NADJ, 128>>>(w);
    wnorm_kernel<<<(NADJ * NADJ) / 256, 256>>>(w);
    prep_all_kernel<<<2049, 256>>>(W1, W2, b1, g1, be1, m1, v1, b2, g2, be2, m2, v2);
    gemm_hmma<1><<<dim3(4, MROWS / 128), 128, SMEM_B>>>(nullptr);
    gemm_hmma<2><<<dim3(4, MROWS / 128), 128, SMEM_B>>>(Wc);
    gcn_kernel<<<128, 512>>>(bc, out);
}